// round 15
// baseline (speedup 1.0000x reference)
#include <cuda_runtime.h>
#include <cuda_fp16.h>
#include <cstdint>

// ---------------- scratch (device globals: no allocs allowed) ----------------
__device__ __align__(1024) __half g_Wt[1024u * 1024u];  // sparsified W^T [N,K] fp16

__device__ __forceinline__ uint32_t smem_u32(const void* p) {
    uint32_t a;
    asm("{ .reg .u64 t; cvta.to.shared.u64 t, %1; cvt.u32.u64 %0, t; }" : "=r"(a) : "l"(p));
    return a;
}

#define CP16(dst, src)                                                      \
    asm volatile("cp.async.cg.shared.global [%0], [%1], 16;"                \
        :: "r"(dst), "l"((uint64_t)__cvta_generic_to_global((const void*)(src))) : "memory")
#define CP_COMMIT()  asm volatile("cp.async.commit_group;" ::: "memory")
#define CP_WAIT1()   asm volatile("cp.async.wait_group 1;" ::: "memory")
#define CP_WAIT2()   asm volatile("cp.async.wait_group 2;" ::: "memory")

__device__ __forceinline__ void ldsm_x4(uint32_t& r0, uint32_t& r1,
                                        uint32_t& r2, uint32_t& r3, uint32_t addr) {
    asm volatile("ldmatrix.sync.aligned.m8n8.x4.shared.b16 {%0,%1,%2,%3}, [%4];"
                 : "=r"(r0), "=r"(r1), "=r"(r2), "=r"(r3) : "r"(addr));
}

__device__ __forceinline__ void mma16816(float* d, const uint32_t* a,
                                         uint32_t b0, uint32_t b1) {
    asm volatile(
        "mma.sync.aligned.m16n8k16.row.col.f32.f16.f16.f32 "
        "{%0,%1,%2,%3}, {%4,%5,%6,%7}, {%8,%9}, {%0,%1,%2,%3};"
        : "+f"(d[0]), "+f"(d[1]), "+f"(d[2]), "+f"(d[3])
        : "r"(a[0]), "r"(a[1]), "r"(a[2]), "r"(a[3]), "r"(b0), "r"(b1));
}

__device__ __forceinline__ void stcs_f2(float* p, float2 v) {
    asm volatile("st.global.cs.v2.f32 [%0], {%1, %2};"
                 :: "l"(__cvta_generic_to_global(p)), "f"(v.x), "f"(v.y) : "memory");
}

// ---------------------------------------------------------------------------
// Prepass (sparsify only): 2:4 sparsify (fp16 semantics) + transpose -> Wt[N,K]
// ---------------------------------------------------------------------------
__global__ void sparsify24_t_kernel(const float* __restrict__ W,
                                    const float* __restrict__ scale,
                                    __half* __restrict__ Wt, int K, int N) {
    __shared__ __half tile[32][40];
    const int t = threadIdx.x;                 // 256 threads
    const int k0 = blockIdx.x * 32, n0 = blockIdx.y * 32;
    const float s = scale[0];

    const int k = t >> 3, gn = t & 7;          // one 4-group per thread
    float4 v = *reinterpret_cast<const float4*>(W + (size_t)(k0 + k) * N + n0 + gn * 4);
    __half h[4];
    h[0] = __float2half_rn(v.x); h[1] = __float2half_rn(v.y);
    h[2] = __float2half_rn(v.z); h[3] = __float2half_rn(v.w);
    float a[4];
#pragma unroll
    for (int i = 0; i < 4; i++) a[i] = fabsf(__half2float(h[i]));
    int imax = 0;
#pragma unroll
    for (int i = 1; i < 4; i++) if (a[i] > a[imax]) imax = i;
    float th = -1.0f;
#pragma unroll
    for (int i = 0; i < 4; i++) if (i != imax && a[i] > th) th = a[i];
#pragma unroll
    for (int i = 0; i < 4; i++)
        tile[gn * 4 + i][k] = (a[i] >= th) ? __float2half_rn(__half2float(h[i]) * s)
                                           : __half(0.0f);
    __syncthreads();

    const int r = t >> 3, c4 = (t & 7) * 4;
    __half o[4];
#pragma unroll
    for (int i = 0; i < 4; i++) o[i] = tile[r][c4 + i];
    *reinterpret_cast<uint2*>(Wt + (size_t)(n0 + r) * K + k0 + c4) =
        *reinterpret_cast<uint2*>(o);
}

// ---------------------------------------------------------------------------
// Fused GEMM: out[M,N] = fp16(X[M,K]) @ Wt[N,K]^T + bias, converting X fp32->
// fp16 in shared memory inside the pipeline (no global Xh pass).
// BM=128, BN=128, BK=32. Rings: A-fp32 x3 (16KB linear), fp16A x2 (16KB,
// 128B-row XOR-swizzled), B x4 (8KB, 64B-row SW64). 256 threads, 2 CTAs/SM.
// ---------------------------------------------------------------------------
#define BM 128
#define BN 128
#define BK 32
#define NIT 32                              // K / BK
#define A32_SLOT 16384
#define F16_SLOT 16384
#define B_SLOT 8192
#define A32_OFF 0
#define F16_OFF (3 * A32_SLOT)              // 49152
#define B_OFF   (F16_OFF + 2 * F16_SLOT)    // 81920
#define DYN_SMEM (B_OFF + 4 * B_SLOT)       // 114688 (112KB)

__device__ __forceinline__ void load_A32(uint32_t dst, const float* Asrc,
                                         int K, int tid) {
#pragma unroll
    for (int i = 0; i < 4; i++) {             // 128 rows x 128B, linear
        int idx = tid + i * 256;              // 0..1023
        int row = idx >> 3, cb = (idx & 7) * 16;
        CP16(dst + (uint32_t)idx * 16,
             reinterpret_cast<const char*>(Asrc + (size_t)row * K) + cb);
    }
}

__device__ __forceinline__ void load_B(uint32_t dst, const __half* Bsrc,
                                       int K, int tid) {
#pragma unroll
    for (int i = 0; i < 2; i++) {             // 128 rows x 64B, SW64
        int idx = tid + i * 256;              // 0..511
        int row = idx >> 2, cb = (idx & 3) * 16;
        uint32_t off = (uint32_t)(row * 64 + cb);
        CP16(dst + (off ^ ((off >> 3) & 0x30)),
             reinterpret_cast<const char*>(Bsrc + (size_t)row * K) + cb);
    }
}

// Convert one fp32 A stage (16KB) to fp16 ldmatrix layout (128B rows, low 64B used)
__device__ __forceinline__ void convert_stage(uint32_t a32, uint32_t f16, int tid) {
#pragma unroll
    for (int i = 0; i < 4; i++) {
        int idx = tid + i * 256;              // fp32 16B chunk index
        float f0, f1, f2, f3;
        asm volatile("ld.shared.v4.f32 {%0,%1,%2,%3}, [%4];"
                     : "=f"(f0), "=f"(f1), "=f"(f2), "=f"(f3)
                     : "r"(a32 + (uint32_t)idx * 16));
        __half2 h0 = __floats2half2_rn(f0, f1);
        __half2 h1 = __floats2half2_rn(f2, f3);
        uint32_t off = (uint32_t)((idx >> 3) * 128 + (idx & 7) * 8);
        uint32_t daddr = f16 + (off ^ ((off >> 3) & 0x70));
        asm volatile("st.shared.v2.b32 [%0], {%1,%2};"
                     :: "r"(daddr),
                        "r"(*reinterpret_cast<uint32_t*>(&h0)),
                        "r"(*reinterpret_cast<uint32_t*>(&h1)) : "memory");
    }
}

__global__ __launch_bounds__(256, 2)
void gemm_fused_kernel(const float* __restrict__ Xf, const __half* __restrict__ Wt,
                       const float* __restrict__ bias, float* __restrict__ out,
                       int M, int N, int K) {
    extern __shared__ __align__(1024) unsigned char dsmem[];

    const int tid = threadIdx.x;
    const int wid = tid >> 5, lane = tid & 31;
    const int wm = wid & 3;                   // m-warp: offset wm*32
    const int wn = wid >> 2;                  // n-warp: offset wn*64
    const int m0 = blockIdx.y * BM;
    const int n0 = blockIdx.x * BN;

    const uint32_t base = smem_u32(dsmem);
    const float*  Abase = Xf + (size_t)m0 * K;
    const __half* Bbase = Wt + (size_t)n0 * K;

    float acc[2][8][4];
#pragma unroll
    for (int i = 0; i < 2; i++)
#pragma unroll
        for (int j = 0; j < 8; j++)
#pragma unroll
            for (int q = 0; q < 4; q++) acc[i][j][q] = 0.0f;

    // ldmatrix per-thread addressing
    const int lrow = lane & 15;
    const uint32_t xrA = (uint32_t)((lrow & 7) * 16);          // A: 128B-row swizzle
    const uint32_t xrB = (uint32_t)(((lrow >> 1) & 3) * 16);   // B: 64B-row SW64
    const uint32_t cbHi = (uint32_t)((lane >> 4) * 16);
    const uint32_t aRowBase = base + F16_OFF + (uint32_t)((wm * 32 + lrow) * 128);
    const uint32_t bRowBase = base + B_OFF + (uint32_t)((wn * 64 + lrow) * 64);

    // prologue: stages 0,1,2 in flight
    load_A32(base + 0 * A32_SLOT, Abase + 0 * BK, K, tid);
    load_B(base + B_OFF + 0 * B_SLOT, Bbase + 0 * BK, K, tid);  CP_COMMIT();
    load_A32(base + 1 * A32_SLOT, Abase + 1 * BK, K, tid);
    load_B(base + B_OFF + 1 * B_SLOT, Bbase + 1 * BK, K, tid);  CP_COMMIT();
    load_A32(base + 2 * A32_SLOT, Abase + 2 * BK, K, tid);
    load_B(base + B_OFF + 2 * B_SLOT, Bbase + 2 * BK, K, tid);  CP_COMMIT();

    CP_WAIT2();
    __syncthreads();
    convert_stage(base + 0 * A32_SLOT, base + F16_OFF + 0 * F16_SLOT, tid);

    uint32_t convOff = 1 * A32_SLOT;          // fp32 slot of stage it+1
    uint32_t cpAOff  = 0;                     // fp32 slot of stage it+3 (= it%3)
    uint32_t bMmaOff = 0;                     // B slot of stage it (= it%4)
    uint32_t cpBOff  = 3 * B_SLOT;            // B slot of stage it+3

    for (int it = 0; it < NIT; it++) {
        CP_WAIT1();
        __syncthreads();   // stage it+1 visible; prior conversions visible

        // convert stage it+1 into the fp16 buffer NOT used by this iter's MMA
        if (it + 1 < NIT)
            convert_stage(base + convOff,
                          base + F16_OFF + (uint32_t)(((it + 1) & 1) * F16_SLOT), tid);

        // prefetch stage it+3
        if (it + 3 < NIT) {
            load_A32(base + cpAOff, Abase + (it + 3) * BK, K, tid);
            load_B(base + B_OFF + cpBOff, Bbase + (it + 3) * BK, K, tid);
        }
        CP_COMMIT();

        // MMA over fp16A buf[it&1] and B slot it%4
        const uint32_t aBufRow = aRowBase + (uint32_t)((it & 1) * F16_SLOT);
        const uint32_t bSlotRow = bRowBase + bMmaOff;
#pragma unroll
        for (int kk = 0; kk < 2; kk++) {
            const uint32_t cb = (uint32_t)(kk * 32) + cbHi;
            uint32_t a[2][4], b[4][4];
#pragma unroll
            for (int mt = 0; mt < 2; mt++)
                ldsm_x4(a[mt][0], a[mt][1], a[mt][2], a[mt][3],
                        aBufRow + (uint32_t)(mt * 2048) + (cb ^ xrA));
#pragma unroll
            for (int ng = 0; ng < 4; ng++)
                ldsm_x4(b[ng][0], b[ng][1], b[ng][2], b[ng][3],
                        bSlotRow + (uint32_t)(ng * 1024) + (cb ^ xrB));
#pragma unroll
            for (int mt = 0; mt < 2; mt++)
#pragma unroll
                for (int ng = 0; ng < 4; ng++) {
                    mma16816(acc[mt][ng * 2 + 0], a[mt], b[ng][0], b[ng][2]);
                    mma16816(acc[mt][ng * 2 + 1], a[mt], b[ng][1], b[ng][3]);
                }
        }

        convOff += A32_SLOT; if (convOff == 3 * A32_SLOT) convOff = 0;
        cpAOff  += A32_SLOT; if (cpAOff  == 3 * A32_SLOT) cpAOff  = 0;
        bMmaOff += B_SLOT;   if (bMmaOff == 4 * B_SLOT)   bMmaOff = 0;
        cpBOff  += B_SLOT;   if (cpBOff  == 4 * B_SLOT)   cpBOff  = 0;
    }

    // epilogue: bias via __ldg, streaming stores (keep x resident in L2)
    const int gid = lane >> 2;
    const int qid = lane & 3;
#pragma unroll
    for (int mt = 0; mt < 2; mt++) {
        const int row0 = m0 + wm * 32 + mt * 16 + gid;
#pragma unroll
        for (int nb = 0; nb < 8; nb++) {
            const int c = wn * 64 + nb * 8 + qid * 2;
            const float2 bv = __ldg(reinterpret_cast<const float2*>(bias + n0 + c));
            float2 v0 = {acc[mt][nb][0] + bv.x, acc[mt][nb][1] + bv.y};
            float2 v1 = {acc[mt][nb][2] + bv.x, acc[mt][nb][3] + bv.y};
            stcs_f2(out + (size_t)row0 * N + n0 + c, v0);
            stcs_f2(out + (size_t)(row0 + 8) * N + n0 + c, v1);
        }
    }
}

// ---------------------------------------------------------------------------
extern "C" void kernel_launch(void* const* d_in, const int* in_sizes, int n_in,
                              void* d_out, int out_size) {
    const float* x      = (const float*)d_in[0];
    const float* weight = (const float*)d_in[1];
    const float* bias   = (const float*)d_in[2];
    const float* scale  = (const float*)d_in[3];
    float* out = (float*)d_out;

    const int N = in_sizes[2];
    const int K = in_sizes[1] / N;
    const int M = in_sizes[0] / K;

    __half* Wt = nullptr;
    cudaGetSymbolAddress((void**)&Wt, g_Wt);

    dim3 sg(K / 32, N / 32);
    sparsify24_t_kernel<<<sg, 256>>>(weight, scale, Wt, K, N);

    cudaFuncSetAttribute(gemm_fused_kernel,
                         cudaFuncAttributeMaxDynamicSharedMemorySize, DYN_SMEM);
    dim3 grid(N / BN, M / BM);
    gemm_fused_kernel<<<grid, 256, DYN_SMEM>>>(x, Wt, bias, out, M, N, K);
}